// round 16
// baseline (speedup 1.0000x reference)
#include <cuda_runtime.h>
#include <cuda_fp16.h>
#include <cstdint>

#define NMAX   50000
#define EH     32
#define NET    3
#define CDIM   96      // NET*EH
#define ABDIM  192     // A(96) | B(96)

// ---- device scratch (static: no allocation allowed) ----
__device__ __half g_ABh[NMAX * ABDIM];   // per-node A|B precompute, fp16 (edge bias folded into A)
__device__ float  g_accum[NMAX * CDIM];  // scatter accumulators (fp32)
__device__ float  g_cnt[NMAX * NET];     // per (node, etype) counts
__device__ __half g_NFh[NMAX * 128];     // nf converted to fp16 (once)
__device__ __half g_Wstage[98304];       // all 4 weight sets staged as [kchunk][n][40] fp16
__device__ int    g_perm[NMAX];          // nodes partitioned by type
__device__ int    g_n0, g_c0, g_c1;      // partition counters

// stage offsets (in halfs)
#define OFF_E0 0
#define OFF_N0 30720
#define OFF_E1 46080
#define OFF_N1 61440

// ===========================================================================
// PTX helpers
// ===========================================================================
__device__ __forceinline__ uint32_t smem_u32(const void* p) {
    uint32_t a;
    asm("{ .reg .u64 t; cvta.to.shared.u64 t, %1; cvt.u32.u64 %0, t; }" : "=r"(a) : "l"(p));
    return a;
}
__device__ __forceinline__ void ldsm4(uint32_t& r0, uint32_t& r1, uint32_t& r2,
                                      uint32_t& r3, uint32_t addr) {
    asm volatile("ldmatrix.sync.aligned.m8n8.x4.shared.b16 {%0,%1,%2,%3}, [%4];"
                 : "=r"(r0), "=r"(r1), "=r"(r2), "=r"(r3) : "r"(addr));
}
#define MMA16816(C, A0, A1, A2, A3, B0, B1) \
    asm volatile("mma.sync.aligned.m16n8k16.row.col.f32.f16.f16.f32 " \
                 "{%0,%1,%2,%3}, {%4,%5,%6,%7}, {%8,%9}, {%0,%1,%2,%3};" \
                 : "+f"((C)[0]), "+f"((C)[1]), "+f"((C)[2]), "+f"((C)[3]) \
                 : "r"(A0), "r"(A1), "r"(A2), "r"(A3), "r"(B0), "r"(B1))
__device__ __forceinline__ uint32_t pack2(float a, float b) {
    __half2 h = __floats2half2_rn(a, b);
    return *reinterpret_cast<uint32_t*>(&h);
}

// ===========================================================================
// Combined weight staging (+ zero partition counters)
// ===========================================================================
__device__ __forceinline__ void stage_edge(const float* eW, int K, int off, int q) {
    int n = q / K, k = q - n * K;
    int half_ = n / CDIM, rem = n % CDIM, t = rem / EH, j = rem % EH;
    float v = eW[(size_t)t * (2 * K * EH) + (size_t)(half_ * K + k) * EH + j];
    g_Wstage[off + (((k >> 5) * ABDIM) + n) * 40 + (k & 31)] = __float2half_rn(v);
}
__device__ __forceinline__ void stage_node(const float* nW, int OUTD, int off, int q) {
    int NR = 2 * OUTD;
    int n = q / CDIM, k = q - n * CDIM;
    int t = n / OUTD, j = n - t * OUTD;
    float v = nW[(size_t)t * CDIM * OUTD + (size_t)k * OUTD + j];
    g_Wstage[off + (((k >> 5) * NR) + n) * 40 + (k & 31)] = __float2half_rn(v);
}
__global__ void prep_all(const float* __restrict__ eW0, const float* __restrict__ nW0,
                         const float* __restrict__ eW1, const float* __restrict__ nW1) {
    int idx = blockIdx.x * blockDim.x + threadIdx.x;
    if (idx == 0) { g_n0 = 0; g_c0 = 0; g_c1 = 0; }
    if (idx < 24576)                  stage_edge(eW0, 128, OFF_E0, idx);
    else if (idx < 24576 + 12288)     stage_node(nW0,  64, OFF_N0, idx - 24576);
    else if (idx < 36864 + 12288)     stage_edge(eW1,  64, OFF_E1, idx - 36864);
    else if (idx < 49152 + 24576)     stage_node(nW1, 128, OFF_N1, idx - 49152);
}
// nf (fp32) -> g_NFh (fp16), once
__global__ void nf2h(const float4* __restrict__ nf4, int tot) {
    int i = blockIdx.x * 256 + threadIdx.x;
    if (i >= tot) return;
    float4 v = nf4[i];
    uint2 u;
    *(__half2*)&u.x = __floats2half2_rn(v.x, v.y);
    *(__half2*)&u.y = __floats2half2_rn(v.z, v.w);
    *(uint2*)(g_NFh + (size_t)i * 4) = u;
}

// ===========================================================================
// Node-type partition (aggregated atomics)
// ===========================================================================
__global__ void count_kernel(const int* __restrict__ nt, int n) {
    int i = blockIdx.x * 256 + threadIdx.x;
    int is0 = (i < n && nt[i] == 0) ? 1 : 0;
    unsigned m = __ballot_sync(0xffffffffu, is0);
    __shared__ int ws[8];
    if ((threadIdx.x & 31) == 0) ws[threadIdx.x >> 5] = __popc(m);
    __syncthreads();
    if (threadIdx.x == 0) {
        int s = 0;
#pragma unroll
        for (int w = 0; w < 8; w++) s += ws[w];
        atomicAdd(&g_n0, s);
    }
}
__global__ void assign_kernel(const int* __restrict__ nt, int n) {
    int i = blockIdx.x * 256 + threadIdx.x;
    int t = (i < n) ? nt[i] : -1;
    unsigned m0 = __ballot_sync(0xffffffffu, t == 0);
    unsigned m1 = __ballot_sync(0xffffffffu, t == 1);
    int lane = threadIdx.x & 31, warp = threadIdx.x >> 5;
    __shared__ int w0[8], w1[8], b0, b1;
    if (lane == 0) { w0[warp] = __popc(m0); w1[warp] = __popc(m1); }
    __syncthreads();
    if (threadIdx.x == 0) {
        int s0 = 0, s1 = 0, o0[8], o1[8];
#pragma unroll
        for (int w = 0; w < 8; w++) { o0[w] = s0; s0 += w0[w]; o1[w] = s1; s1 += w1[w]; }
#pragma unroll
        for (int w = 0; w < 8; w++) { w0[w] = o0[w]; w1[w] = o1[w]; }
        b0 = atomicAdd(&g_c0, s0);
        b1 = atomicAdd(&g_c1, s1);
    }
    __syncthreads();
    unsigned lt = (1u << lane) - 1u;
    if (t == 0)      g_perm[b0 + w0[warp] + __popc(m0 & lt)] = i;
    else if (t == 1) g_perm[g_n0 + b1 + w1[warp] + __popc(m1 & lt)] = i;
}

// ===========================================================================
// AB GEMM layer 0 (fp16 X from g_NFh): 128 rows/blk, CHUNK=96 slab per
// blockIdx.y. Slab 0 folds edge bias and zeroes accum+cnt.
// ===========================================================================
template <int K, int NTOT, int CHUNK, int WOFF>
__global__ __launch_bounds__(256) void ab_gemm(const __half* __restrict__ X,
                                               const float* __restrict__ bias, int n) {
    constexpr int NB = CHUNK / 8;
    constexpr int NKC = K / 32;
    constexpr int XSH = K + 8;
    extern __shared__ __align__(16) char sm[];
    __half* Xs = (__half*)sm;                   // [128][XSH]
    __half* Ws = (__half*)(sm + 128 * XSH * 2); // [NKC][CHUNK][40]

    const int tid = threadIdx.x;
    const int lane = tid & 31, wid = tid >> 5;
    const int gid = lane >> 2, tig = lane & 3;
    const int base = blockIdx.x * 128;
    const int cb = blockIdx.y * CHUNK;
    const int wr = wid * 16;

    {
        const __half* wsrc = g_Wstage + WOFF;
        int4* wdst = (int4*)Ws;
        for (int idx = tid; idx < NKC * CHUNK * 5; idx += 256) {
            int kc = idx / (CHUNK * 5), r = idx - kc * (CHUNK * 5);
            wdst[idx] = ((const int4*)(wsrc + (size_t)(kc * NTOT + cb) * 40))[r];
        }
    }
    {
        constexpr int K8 = K / 8;
#pragma unroll
        for (int i = 0; i < 128 * K8 / 256; i++) {
            int idx = tid + i * 256;
            int row = idx / K8, k8 = idx - row * K8;
            int grow = min(base + row, n - 1);
            *(int4*)&Xs[row * XSH + k8 * 8] = *(const int4*)(X + (size_t)grow * K + k8 * 8);
        }
    }
    __syncthreads();

    const uint32_t aBase = smem_u32(Xs) +
        (((wr + (lane & 15)) * XSH + ((lane >> 4) << 3)) << 1);
    const uint32_t bBase = smem_u32(Ws) +
        (((((lane >> 4) << 3) + (lane & 7)) * 40 + (((lane >> 3) & 1) << 3)) << 1);

    float c[NB][4];
#pragma unroll
    for (int nb = 0; nb < NB; nb++)
#pragma unroll
        for (int q = 0; q < 4; q++) c[nb][q] = 0.f;

#pragma unroll
    for (int kc = 0; kc < NKC; kc++)
#pragma unroll
        for (int ks = 0; ks < 2; ks++) {
            uint32_t a0, a1, a2, a3;
            ldsm4(a0, a1, a2, a3, aBase + ((kc * 32 + ks * 16) << 1));
#pragma unroll
            for (int p = 0; p < NB / 2; p++) {
                uint32_t b0, b1, b2, b3;
                ldsm4(b0, b1, b2, b3,
                      bBase + ((((kc * CHUNK + p * 16) * 40) + ks * 16) << 1));
                MMA16816(c[2 * p],     a0, a1, a2, a3, b0, b1);
                MMA16816(c[2 * p + 1], a0, a1, a2, a3, b2, b3);
            }
        }

#pragma unroll
    for (int h = 0; h < 2; h++) {
        int row = base + wr + gid + 8 * h;
        if (row < n) {
#pragma unroll
            for (int nb = 0; nb < NB; nb++) {
                int col = cb + nb * 8 + 2 * tig;
                float vx = c[nb][2 * h], vy = c[nb][2 * h + 1];
                if (blockIdx.y == 0) {
                    float2 b = *(const float2*)(bias + col);
                    vx += b.x; vy += b.y;
                }
                *(__half2*)(g_ABh + (size_t)row * ABDIM + col) = __floats2half2_rn(vx, vy);
            }
        }
    }
    if (blockIdx.y == 0) {
        float4 z = make_float4(0.f, 0.f, 0.f, 0.f);
        for (int idx = lane; idx < 16 * 24; idx += 32) {
            int r = idx / 24, q = idx - r * 24;
            int row = base + wr + r;
            if (row < n) ((float4*)(g_accum + (size_t)row * CDIM))[q] = z;
        }
        if (lane < 16) {
            int row = base + wr + lane;
            if (row < n) {
                g_cnt[row * NET] = 0.f;
                g_cnt[row * NET + 1] = 0.f;
                g_cnt[row * NET + 2] = 0.f;
            }
        }
    }
}

// ===========================================================================
// FUSED node-GEMM-0 + AB-GEMM-1 (type-partitioned rows, perm scatter).
// Phase 1: H = relu(mean @ nW0[t] + nb0[t])   (cH in registers, K=96, OUTD=64)
// Bounce H -> smem fp16, then
// Phase 2: AB1 = H @ eW1^T (192 cols, 2 slabs of 96 seq.), eb1 folded slab 0.
// Also re-zeroes g_accum rows for the layer-1 edge pass.
// ===========================================================================
__global__ __launch_bounds__(256) void node_ab_gemm(const float* __restrict__ X,
                                                    const float* __restrict__ cnt,
                                                    const float* __restrict__ nbias,
                                                    const float* __restrict__ ebias, int n) {
    constexpr int XSH = 104;                 // 96 + 8
    constexpr int HSH = 72;                  // 64 + 8
    extern __shared__ __align__(16) char sm[];
    __half* Xs  = (__half*)sm;               // [128][104]  26624 B
    __half* W0s = (__half*)(sm + 26624);     // [3][64][40] 15360 B
    __half* Hs  = (__half*)(sm + 41984);     // [128][72]   18432 B
    __half* W1s = (__half*)(sm + 60416);     // [2][192][40]30720 B

    const int n0 = g_n0;
    const int nblk0 = (n0 + 127) >> 7;
    const int nblk1 = (n - n0 + 127) >> 7;
    if ((int)blockIdx.x >= nblk0 + nblk1) return;
    const int t = ((int)blockIdx.x < nblk0) ? 0 : 1;
    const int pb = (t == 0) ? (int)blockIdx.x * 128 : n0 + ((int)blockIdx.x - nblk0) * 128;
    const int plim = (t == 0) ? n0 : n;

    const int tid = threadIdx.x;
    const int lane = tid & 31, wid = tid >> 5;
    const int gid = lane >> 2, tig = lane & 3;
    const int wr = wid * 16;

    // ---- W0 (type slab) + full W1 ----
    {
        const __half* w0 = g_Wstage + OFF_N0;
        int4* d0 = (int4*)W0s;
        for (int idx = tid; idx < 3 * 64 * 5; idx += 256) {
            int kc = idx / 320, r = idx - kc * 320;
            d0[idx] = ((const int4*)(w0 + (size_t)(kc * 128 + t * 64) * 40))[r];
        }
        const int4* w1 = (const int4*)(g_Wstage + OFF_E1);
        int4* d1 = (int4*)W1s;
        for (int idx = tid; idx < 2 * 192 * 5; idx += 256) d1[idx] = w1[idx];
    }
    // ---- X tile: gather perm rows, scale by 1/cnt, -> fp16 smem ----
#pragma unroll
    for (int i = 0; i < 128 * 24 / 256; i++) {
        int idx = tid + i * 256;
        int row = idx / 24, k4 = idx - row * 24;
        int grow = g_perm[min(pb + row, plim - 1)];
        float s = 1.0f / fmaxf(cnt[grow * NET + (k4 >> 3)], 1.0f);
        float4 v = *(const float4*)(X + (size_t)grow * CDIM + k4 * 4);
        uint2 u;
        *(__half2*)&u.x = __floats2half2_rn(v.x * s, v.y * s);
        *(__half2*)&u.y = __floats2half2_rn(v.z * s, v.w * s);
        *(uint2*)&Xs[row * XSH + k4 * 4] = u;
    }
    __syncthreads();

    // re-zero g_accum rows for the layer-1 edge pass (reads done above)
    {
        float4 z = make_float4(0.f, 0.f, 0.f, 0.f);
#pragma unroll
        for (int i = 0; i < 12; i++) {
            int idx = tid + i * 256;
            int r = idx / 24, q = idx - r * 24;
            int pos = pb + r;
            if (pos < plim) ((float4*)(g_accum + (size_t)g_perm[pos] * CDIM))[q] = z;
        }
    }

    const uint32_t aBase = smem_u32(Xs) +
        (((wr + (lane & 15)) * XSH + ((lane >> 4) << 3)) << 1);
    const uint32_t bBase0 = smem_u32(W0s) +
        (((((lane >> 4) << 3) + (lane & 7)) * 40 + (((lane >> 3) & 1) << 3)) << 1);

    // ---- phase 1: K=96, OUTD=64 ----
    float cH[8][4];
#pragma unroll
    for (int nb = 0; nb < 8; nb++)
#pragma unroll
        for (int q = 0; q < 4; q++) cH[nb][q] = 0.f;

#pragma unroll
    for (int kc = 0; kc < 3; kc++)
#pragma unroll
        for (int ks = 0; ks < 2; ks++) {
            uint32_t a0, a1, a2, a3;
            ldsm4(a0, a1, a2, a3, aBase + ((kc * 32 + ks * 16) << 1));
#pragma unroll
            for (int p = 0; p < 4; p++) {
                uint32_t b0, b1, b2, b3;
                ldsm4(b0, b1, b2, b3,
                      bBase0 + ((((kc * 64 + p * 16) * 40) + ks * 16) << 1));
                MMA16816(cH[2 * p],     a0, a1, a2, a3, b0, b1);
                MMA16816(cH[2 * p + 1], a0, a1, a2, a3, b2, b3);
            }
        }

    // bias + relu in registers, bounce to Hs (fp16)
#pragma unroll
    for (int nb = 0; nb < 8; nb++) {
        int col = nb * 8 + 2 * tig;
        float2 b = *(const float2*)(nbias + t * 64 + col);
#pragma unroll
        for (int h = 0; h < 2; h++) {
            float vx = fmaxf(cH[nb][2 * h] + b.x, 0.f);
            float vy = fmaxf(cH[nb][2 * h + 1] + b.y, 0.f);
            *(__half2*)&Hs[(wr + gid + 8 * h) * HSH + col] = __floats2half2_rn(vx, vy);
        }
    }
    __syncthreads();

    // ---- phase 2: AB1 = H @ W1^T, K=64, 2 slabs of 96 cols ----
    const uint32_t aBase2 = smem_u32(Hs) +
        (((wr + (lane & 15)) * HSH + ((lane >> 4) << 3)) << 1);
    const uint32_t bBase1 = smem_u32(W1s) +
        (((((lane >> 4) << 3) + (lane & 7)) * 40 + (((lane >> 3) & 1) << 3)) << 1);

#pragma unroll
    for (int s = 0; s < 2; s++) {
        float c2[12][4];
#pragma unroll
        for (int nb = 0; nb < 12; nb++)
#pragma unroll
            for (int q = 0; q < 4; q++) c2[nb][q] = 0.f;

#pragma unroll
        for (int kc = 0; kc < 2; kc++)
#pragma unroll
            for (int ks = 0; ks < 2; ks++) {
                uint32_t a0, a1, a2, a3;
                ldsm4(a0, a1, a2, a3, aBase2 + ((kc * 32 + ks * 16) << 1));
#pragma unroll
                for (int p = 0; p < 6; p++) {
                    uint32_t b0, b1, b2, b3;
                    ldsm4(b0, b1, b2, b3,
                          bBase1 + ((((kc * 192 + s * 96 + p * 16) * 40) + ks * 16) << 1));
                    MMA16816(c2[2 * p],     a0, a1, a2, a3, b0, b1);
                    MMA16816(c2[2 * p + 1], a0, a1, a2, a3, b2, b3);
                }
            }

#pragma unroll
        for (int h = 0; h < 2; h++) {
            int pos = pb + wr + gid + 8 * h;
            if (pos < plim) {
                int row = g_perm[pos];
#pragma unroll
                for (int nb = 0; nb < 12; nb++) {
                    int col = s * 96 + nb * 8 + 2 * tig;
                    float vx = c2[nb][2 * h], vy = c2[nb][2 * h + 1];
                    if (s == 0) {                   // A half: fold eb1
                        float2 b = *(const float2*)(ebias + col);
                        vx += b.x; vy += b.y;
                    }
                    *(__half2*)(g_ABh + (size_t)row * ABDIM + col) = __floats2half2_rn(vx, vy);
                }
            }
        }
    }
}

// ===========================================================================
// Node GEMM layer 1 (final, fp32 out): type-partitioned, perm scatter.
// ===========================================================================
template <int NTOT, int OUTD, int WOFF>
__global__ __launch_bounds__(256) void node_gemm(const float* __restrict__ X,
                                                 const float* __restrict__ cnt,
                                                 const float* __restrict__ bias,
                                                 float* __restrict__ out, int n) {
    constexpr int NB = OUTD / 8;
    constexpr int XSH = 104;
    extern __shared__ __align__(16) char sm[];
    __half* Xs = (__half*)sm;
    __half* Ws = (__half*)(sm + 128 * XSH * 2);

    const int n0 = g_n0;
    const int nblk0 = (n0 + 127) >> 7;
    const int nblk1 = (n - n0 + 127) >> 7;
    if ((int)blockIdx.x >= nblk0 + nblk1) return;
    const int t = ((int)blockIdx.x < nblk0) ? 0 : 1;
    const int pb = (t == 0) ? (int)blockIdx.x * 128 : n0 + ((int)blockIdx.x - nblk0) * 128;
    const int plim = (t == 0) ? n0 : n;

    const int tid = threadIdx.x;
    const int lane = tid & 31, wid = tid >> 5;
    const int gid = lane >> 2, tig = lane & 3;
    const int wr = wid * 16;
    const int cb = t * OUTD;

    {
        const __half* wsrc = g_Wstage + WOFF;
        int4* wdst = (int4*)Ws;
        for (int idx = tid; idx < 3 * OUTD * 5; idx += 256) {
            int kc = idx / (OUTD * 5), r = idx - kc * (OUTD * 5);
            wdst[idx] = ((const int4*)(wsrc + (size_t)(kc * NTOT + cb) * 40))[r];
        }
    }
#pragma unroll
    for (int i = 0; i < 128 * 24 / 256; i++) {
        int idx = tid + i * 256;
        int row = idx / 24, k4 = idx - row * 24;
        int grow = g_perm[min(pb + row, plim - 1)];
        float s = 1.0f / fmaxf(cnt[grow * NET + (k4 >> 3)], 1.0f);
        float4 v = *(const float4*)(X + (size_t)grow * CDIM + k4 * 4);
        uint2 u;
        *(__half2*)&u.x = __floats2half2_rn(v.x * s, v.y * s);
        *(__half2*)&u.y = __floats2half2_rn(v.z * s, v.w * s);
        *(uint2*)&Xs[row * XSH + k4 * 4] = u;
    }
    __syncthreads();

    const uint32_t aBase = smem_u32(Xs) +
        (((wr + (lane & 15)) * XSH + ((lane >> 4) << 3)) << 1);
    const uint32_t bBase = smem_u32(Ws) +
        (((((lane >> 4) << 3) + (lane & 7)) * 40 + (((lane >> 3) & 1) << 3)) << 1);

    float c[NB][4];
#pragma unroll
    for (int nb = 0; nb < NB; nb++)
#pragma unroll
        for (int q = 0; q < 4; q++) c[nb][q] = 0.f;

#pragma unroll
    for (int kc = 0; kc < 3; kc++)
#pragma unroll
        for (int ks = 0; ks < 2; ks++) {
            uint32_t a0, a1, a2, a3;
            ldsm4(a0, a1, a2, a3, aBase + ((kc * 32 + ks * 16) << 1));
#pragma unroll
            for (int p = 0; p < NB / 2; p++) {
                uint32_t b0, b1, b2, b3;
                ldsm4(b0, b1, b2, b3,
                      bBase + ((((kc * OUTD + p * 16) * 40) + ks * 16) << 1));
                MMA16816(c[2 * p],     a0, a1, a2, a3, b0, b1);
                MMA16816(c[2 * p + 1], a0, a1, a2, a3, b2, b3);
            }
        }

#pragma unroll
    for (int h = 0; h < 2; h++) {
        int pos = pb + wr + gid + 8 * h;
        if (pos < plim) {
            int row = g_perm[pos];
#pragma unroll
            for (int nb = 0; nb < NB; nb++) {
                int col = nb * 8 + 2 * tig;
                float2 b = *(const float2*)(bias + t * OUTD + col);
                float vx = fmaxf(c[nb][2 * h] + b.x, 0.f);
                float vy = fmaxf(c[nb][2 * h + 1] + b.y, 0.f);
                *(float2*)(out + (size_t)row * OUTD + col) = make_float2(vx, vy);
            }
        }
    }
}

// ===========================================================================
// Edge pass: 8 threads / edge, fp16 gathers, fp32 RED scatter.
// ===========================================================================
template <bool COUNT>
__global__ __launch_bounds__(256) void edge_kernel(const int* __restrict__ ei,
                                                   const int* __restrict__ et, int E) {
    int gid = blockIdx.x * blockDim.x + threadIdx.x;
    int e = gid >> 3;
    if (e >= E) return;
    int l = gid & 7;
    int src = ei[e], dst = ei[E + e], t = et[e];

    uint2 ar = *(const uint2*)(g_ABh + (size_t)src * ABDIM + t * EH + l * 4);
    uint2 br = *(const uint2*)(g_ABh + (size_t)dst * ABDIM + CDIM + t * EH + l * 4);
    float2 a0 = __half22float2(*(__half2*)&ar.x);
    float2 a1 = __half22float2(*(__half2*)&ar.y);
    float2 b0 = __half22float2(*(__half2*)&br.x);
    float2 b1 = __half22float2(*(__half2*)&br.y);
    float mx = fmaxf(a0.x + b0.x, 0.f);
    float my = fmaxf(a0.y + b0.y, 0.f);
    float mz = fmaxf(a1.x + b1.x, 0.f);
    float mw = fmaxf(a1.y + b1.y, 0.f);

    float* p = g_accum + (size_t)dst * CDIM + t * EH + l * 4;
    asm volatile("red.global.add.v4.f32 [%0], {%1,%2,%3,%4};"
                 :: "l"(p), "f"(mx), "f"(my), "f"(mz), "f"(mw) : "memory");
    if (COUNT && l == 0) atomicAdd(g_cnt + (size_t)dst * NET + t, 1.0f);
}

// ===========================================================================
extern "C" void kernel_launch(void* const* d_in, const int* in_sizes, int n_in,
                              void* d_out, int out_size) {
    const float* nf  = (const float*)d_in[0];
    const int*   ei  = (const int*)  d_in[1];
    const int*   et  = (const int*)  d_in[2];
    const int*   nt  = (const int*)  d_in[3];
    const float* eW0 = (const float*)d_in[4];
    const float* eb0 = (const float*)d_in[5];
    const float* nW0 = (const float*)d_in[6];
    const float* nb0 = (const float*)d_in[7];
    const float* eW1 = (const float*)d_in[8];
    const float* eb1 = (const float*)d_in[9];
    const float* nW1 = (const float*)d_in[10];
    const float* nb1 = (const float*)d_in[11];
    float* out = (float*)d_out;

    const int N = in_sizes[3];
    const int E = in_sizes[2];

    float *pAcc, *pCnt;
    __half *pNFh;
    cudaGetSymbolAddress((void**)&pAcc, g_accum);
    cudaGetSymbolAddress((void**)&pCnt, g_cnt);
    cudaGetSymbolAddress((void**)&pNFh, g_NFh);

    const int nb128 = (N + 127) / 128;
    const dim3 g2(nb128, 2);
    const int gNode = nb128 + 1;
    const int gEdge = (E * 8 + 255) / 256;
    const int gN = (N + 255) / 256;

    constexpr int S_AB0 = 128 * 136 * 2 + 4 * 96 * 40 * 2;   // 65536
    constexpr int S_NAB = 91136;                             // fused node0+ab1
    constexpr int S_N1  = 128 * 104 * 2 + 3 * 128 * 40 * 2;  // 57344
    cudaFuncSetAttribute(ab_gemm<128, 192, 96, OFF_E0>,
                         cudaFuncAttributeMaxDynamicSharedMemorySize, S_AB0);
    cudaFuncSetAttribute(node_ab_gemm,
                         cudaFuncAttributeMaxDynamicSharedMemorySize, S_NAB);
    cudaFuncSetAttribute(node_gemm<256, 128, OFF_N1>,
                         cudaFuncAttributeMaxDynamicSharedMemorySize, S_N1);

    // staging, nf->fp16, node-type partition
    prep_all<<<(73728 + 255) / 256, 256>>>(eW0, nW0, eW1, nW1);
    nf2h<<<(N * 32 + 255) / 256, 256>>>((const float4*)nf, N * 32);
    count_kernel<<<gN, 256>>>(nt, N);
    assign_kernel<<<gN, 256>>>(nt, N);

    // ---------------- layer 0 (128 -> 64) ----------------
    ab_gemm<128, 192, 96, OFF_E0><<<g2, 256, S_AB0>>>(pNFh, eb0, N);
    edge_kernel<true><<<gEdge, 256>>>(ei, et, E);
    // fused: node0 + ab1 (+ re-zero accum for layer-1 edges)
    node_ab_gemm<<<gNode, 256, S_NAB>>>(pAcc, pCnt, nb0, eb1, N);

    // ---------------- layer 1 (64 -> 128) ----------------
    edge_kernel<false><<<gEdge, 256>>>(ei, et, E);
    node_gemm<256, 128, OFF_N1><<<gNode, 256, S_N1>>>(pAcc, pCnt, nb1, out, N);
}

// round 17
// speedup vs baseline: 1.3535x; 1.3535x over previous
#include <cuda_runtime.h>
#include <cuda_fp16.h>
#include <cstdint>

#define NMAX   50000
#define EH     32
#define NET    3
#define CDIM   96      // NET*EH
#define ABDIM  192     // A(96) | B(96)

// ---- device scratch (static: no allocation allowed) ----
__device__ __half g_ABh[NMAX * ABDIM];   // per-node A|B precompute, fp16 (edge bias folded into A)
__device__ float  g_accum[NMAX * CDIM];  // scatter accumulators (fp32)
__device__ float  g_cnt[NMAX * NET];     // per (node, etype) counts
__device__ __half g_Hh[NMAX * 64];       // layer-0 node output (fp16)
__device__ __half g_NFh[NMAX * 128];     // nf converted to fp16 (once)
__device__ __half g_Wstage[98304];       // all 4 weight sets staged as [kchunk][n][40] fp16
__device__ int    g_perm[NMAX];          // nodes partitioned by type
__device__ int    g_n0, g_c0, g_c1;      // partition counters

// stage offsets (in halfs)
#define OFF_E0 0
#define OFF_N0 30720
#define OFF_E1 46080
#define OFF_N1 61440

// ===========================================================================
// PTX helpers
// ===========================================================================
__device__ __forceinline__ uint32_t smem_u32(const void* p) {
    uint32_t a;
    asm("{ .reg .u64 t; cvta.to.shared.u64 t, %1; cvt.u32.u64 %0, t; }" : "=r"(a) : "l"(p));
    return a;
}
__device__ __forceinline__ void ldsm4(uint32_t& r0, uint32_t& r1, uint32_t& r2,
                                      uint32_t& r3, uint32_t addr) {
    asm volatile("ldmatrix.sync.aligned.m8n8.x4.shared.b16 {%0,%1,%2,%3}, [%4];"
                 : "=r"(r0), "=r"(r1), "=r"(r2), "=r"(r3) : "r"(addr));
}
#define MMA16816(C, A0, A1, A2, A3, B0, B1) \
    asm volatile("mma.sync.aligned.m16n8k16.row.col.f32.f16.f16.f32 " \
                 "{%0,%1,%2,%3}, {%4,%5,%6,%7}, {%8,%9}, {%0,%1,%2,%3};" \
                 : "+f"((C)[0]), "+f"((C)[1]), "+f"((C)[2]), "+f"((C)[3]) \
                 : "r"(A0), "r"(A1), "r"(A2), "r"(A3), "r"(B0), "r"(B1))

// ===========================================================================
// Combined weight staging (+ zero partition counters)
// ===========================================================================
__device__ __forceinline__ void stage_edge(const float* eW, int K, int off, int q) {
    int n = q / K, k = q - n * K;
    int half_ = n / CDIM, rem = n % CDIM, t = rem / EH, j = rem % EH;
    float v = eW[(size_t)t * (2 * K * EH) + (size_t)(half_ * K + k) * EH + j];
    g_Wstage[off + (((k >> 5) * ABDIM) + n) * 40 + (k & 31)] = __float2half_rn(v);
}
__device__ __forceinline__ void stage_node(const float* nW, int OUTD, int off, int q) {
    int NR = 2 * OUTD;
    int n = q / CDIM, k = q - n * CDIM;
    int t = n / OUTD, j = n - t * OUTD;
    float v = nW[(size_t)t * CDIM * OUTD + (size_t)k * OUTD + j];
    g_Wstage[off + (((k >> 5) * NR) + n) * 40 + (k & 31)] = __float2half_rn(v);
}
__global__ void prep_all(const float* __restrict__ eW0, const float* __restrict__ nW0,
                         const float* __restrict__ eW1, const float* __restrict__ nW1) {
    int idx = blockIdx.x * blockDim.x + threadIdx.x;
    if (idx == 0) { g_n0 = 0; g_c0 = 0; g_c1 = 0; }
    if (idx < 24576)                  stage_edge(eW0, 128, OFF_E0, idx);
    else if (idx < 24576 + 12288)     stage_node(nW0,  64, OFF_N0, idx - 24576);
    else if (idx < 36864 + 12288)     stage_edge(eW1,  64, OFF_E1, idx - 36864);
    else if (idx < 49152 + 24576)     stage_node(nW1, 128, OFF_N1, idx - 49152);
}
// nf (fp32) -> g_NFh (fp16), once
__global__ void nf2h(const float4* __restrict__ nf4, int tot) {
    int i = blockIdx.x * 256 + threadIdx.x;
    if (i >= tot) return;
    float4 v = nf4[i];
    uint2 u;
    *(__half2*)&u.x = __floats2half2_rn(v.x, v.y);
    *(__half2*)&u.y = __floats2half2_rn(v.z, v.w);
    *(uint2*)(g_NFh + (size_t)i * 4) = u;
}

// ===========================================================================
// Node-type partition (aggregated atomics)
// ===========================================================================
__global__ void count_kernel(const int* __restrict__ nt, int n) {
    int i = blockIdx.x * 256 + threadIdx.x;
    int is0 = (i < n && nt[i] == 0) ? 1 : 0;
    unsigned m = __ballot_sync(0xffffffffu, is0);
    __shared__ int ws[8];
    if ((threadIdx.x & 31) == 0) ws[threadIdx.x >> 5] = __popc(m);
    __syncthreads();
    if (threadIdx.x == 0) {
        int s = 0;
#pragma unroll
        for (int w = 0; w < 8; w++) s += ws[w];
        atomicAdd(&g_n0, s);
    }
}
__global__ void assign_kernel(const int* __restrict__ nt, int n) {
    int i = blockIdx.x * 256 + threadIdx.x;
    int t = (i < n) ? nt[i] : -1;
    unsigned m0 = __ballot_sync(0xffffffffu, t == 0);
    unsigned m1 = __ballot_sync(0xffffffffu, t == 1);
    int lane = threadIdx.x & 31, warp = threadIdx.x >> 5;
    __shared__ int w0[8], w1[8], b0, b1;
    if (lane == 0) { w0[warp] = __popc(m0); w1[warp] = __popc(m1); }
    __syncthreads();
    if (threadIdx.x == 0) {
        int s0 = 0, s1 = 0, o0[8], o1[8];
#pragma unroll
        for (int w = 0; w < 8; w++) { o0[w] = s0; s0 += w0[w]; o1[w] = s1; s1 += w1[w]; }
#pragma unroll
        for (int w = 0; w < 8; w++) { w0[w] = o0[w]; w1[w] = o1[w]; }
        b0 = atomicAdd(&g_c0, s0);
        b1 = atomicAdd(&g_c1, s1);
    }
    __syncthreads();
    unsigned lt = (1u << lane) - 1u;
    if (t == 0)      g_perm[b0 + w0[warp] + __popc(m0 & lt)] = i;
    else if (t == 1) g_perm[g_n0 + b1 + w1[warp] + __popc(m1 & lt)] = i;
}

// ===========================================================================
// AB GEMM (fp16 X input): 128 rows/blk, 256 thr, CHUNK-wide slab per
// blockIdx.y. Slab 0 folds edge bias + zeroes accum (+cnt when ZCNT).
// ===========================================================================
template <int K, int NTOT, int CHUNK, int WOFF, bool ZCNT>
__global__ __launch_bounds__(256) void ab_gemm(const __half* __restrict__ X,
                                               const float* __restrict__ bias, int n) {
    constexpr int NB = CHUNK / 8;
    constexpr int NKC = K / 32;
    constexpr int XSH = K + 8;
    extern __shared__ __align__(16) char sm[];
    __half* Xs = (__half*)sm;                   // [128][XSH]
    __half* Ws = (__half*)(sm + 128 * XSH * 2); // [NKC][CHUNK][40]

    const int tid = threadIdx.x;
    const int lane = tid & 31, wid = tid >> 5;
    const int gid = lane >> 2, tig = lane & 3;
    const int base = blockIdx.x * 128;
    const int cb = blockIdx.y * CHUNK;
    const int wr = wid * 16;

    {
        const __half* wsrc = g_Wstage + WOFF;
        int4* wdst = (int4*)Ws;
        for (int idx = tid; idx < NKC * CHUNK * 5; idx += 256) {
            int kc = idx / (CHUNK * 5), r = idx - kc * (CHUNK * 5);
            wdst[idx] = ((const int4*)(wsrc + (size_t)(kc * NTOT + cb) * 40))[r];
        }
    }
    {
        constexpr int K8 = K / 8;
#pragma unroll
        for (int i = 0; i < 128 * K8 / 256; i++) {
            int idx = tid + i * 256;
            int row = idx / K8, k8 = idx - row * K8;
            int grow = min(base + row, n - 1);
            *(int4*)&Xs[row * XSH + k8 * 8] = *(const int4*)(X + (size_t)grow * K + k8 * 8);
        }
    }
    __syncthreads();

    const uint32_t aBase = smem_u32(Xs) +
        (((wr + (lane & 15)) * XSH + ((lane >> 4) << 3)) << 1);
    const uint32_t bBase = smem_u32(Ws) +
        (((((lane >> 4) << 3) + (lane & 7)) * 40 + (((lane >> 3) & 1) << 3)) << 1);

    float c[NB][4];
#pragma unroll
    for (int nb = 0; nb < NB; nb++)
#pragma unroll
        for (int q = 0; q < 4; q++) c[nb][q] = 0.f;

#pragma unroll
    for (int kc = 0; kc < NKC; kc++)
#pragma unroll
        for (int ks = 0; ks < 2; ks++) {
            uint32_t a0, a1, a2, a3;
            ldsm4(a0, a1, a2, a3, aBase + ((kc * 32 + ks * 16) << 1));
#pragma unroll
            for (int p = 0; p < NB / 2; p++) {
                uint32_t b0, b1, b2, b3;
                ldsm4(b0, b1, b2, b3,
                      bBase + ((((kc * CHUNK + p * 16) * 40) + ks * 16) << 1));
                MMA16816(c[2 * p],     a0, a1, a2, a3, b0, b1);
                MMA16816(c[2 * p + 1], a0, a1, a2, a3, b2, b3);
            }
        }

#pragma unroll
    for (int h = 0; h < 2; h++) {
        int row = base + wr + gid + 8 * h;
        if (row < n) {
#pragma unroll
            for (int nb = 0; nb < NB; nb++) {
                int col = cb + nb * 8 + 2 * tig;
                float vx = c[nb][2 * h], vy = c[nb][2 * h + 1];
                if (blockIdx.y == 0) {              // A half: fold edge bias
                    float2 b = *(const float2*)(bias + col);
                    vx += b.x; vy += b.y;
                }
                *(__half2*)(g_ABh + (size_t)row * ABDIM + col) = __floats2half2_rn(vx, vy);
            }
        }
    }
    // fused zeroing of scatter state (slab 0)
    if (blockIdx.y == 0) {
        float4 z = make_float4(0.f, 0.f, 0.f, 0.f);
        for (int idx = lane; idx < 16 * 24; idx += 32) {
            int r = idx / 24, q = idx - r * 24;
            int row = base + wr + r;
            if (row < n) ((float4*)(g_accum + (size_t)row * CDIM))[q] = z;
        }
        if (ZCNT && lane < 16) {
            int row = base + wr + lane;
            if (row < n) {
                g_cnt[row * NET] = 0.f;
                g_cnt[row * NET + 1] = 0.f;
                g_cnt[row * NET + 2] = 0.f;
            }
        }
    }
}

// ===========================================================================
// Node GEMM over type-partitioned rows (perm scatter), smem X (mean folded).
// ===========================================================================
template <int NTOT, int OUTD, int WOFF, bool HOUT>
__global__ __launch_bounds__(256) void node_gemm(const float* __restrict__ X,
                                                 const float* __restrict__ cnt,
                                                 const float* __restrict__ bias,
                                                 float* __restrict__ out, int n) {
    constexpr int NB = OUTD / 8;
    constexpr int NKC = 3;                 // K = 96
    constexpr int XSH = 104;               // 96 + 8 pad
    extern __shared__ __align__(16) char sm[];
    __half* Xs = (__half*)sm;                   // [128][104]
    __half* Ws = (__half*)(sm + 128 * XSH * 2); // [3][OUTD][40]

    const int n0 = g_n0;
    const int nblk0 = (n0 + 127) >> 7;
    const int nblk1 = (n - n0 + 127) >> 7;
    if ((int)blockIdx.x >= nblk0 + nblk1) return;
    const int t = ((int)blockIdx.x < nblk0) ? 0 : 1;
    const int pb = (t == 0) ? (int)blockIdx.x * 128 : n0 + ((int)blockIdx.x - nblk0) * 128;
    const int plim = (t == 0) ? n0 : n;

    const int tid = threadIdx.x;
    const int lane = tid & 31, wid = tid >> 5;
    const int gid = lane >> 2, tig = lane & 3;
    const int wr = wid * 16;
    const int cb = t * OUTD;

    {
        const __half* wsrc = g_Wstage + WOFF;
        int4* wdst = (int4*)Ws;
        for (int idx = tid; idx < NKC * OUTD * 5; idx += 256) {
            int kc = idx / (OUTD * 5), r = idx - kc * (OUTD * 5);
            wdst[idx] = ((const int4*)(wsrc + (size_t)(kc * NTOT + cb) * 40))[r];
        }
    }
#pragma unroll
    for (int i = 0; i < 128 * 24 / 256; i++) {
        int idx = tid + i * 256;
        int row = idx / 24, k4 = idx - row * 24;
        int grow = g_perm[min(pb + row, plim - 1)];
        float s = 1.0f / fmaxf(cnt[grow * NET + (k4 >> 3)], 1.0f);
        float4 v = *(const float4*)(X + (size_t)grow * CDIM + k4 * 4);
        uint2 u;
        *(__half2*)&u.x = __floats2half2_rn(v.x * s, v.y * s);
        *(__half2*)&u.y = __floats2half2_rn(v.z * s, v.w * s);
        *(uint2*)&Xs[row * XSH + k4 * 4] = u;
    }
    __syncthreads();

    const uint32_t aBase = smem_u32(Xs) +
        (((wr + (lane & 15)) * XSH + ((lane >> 4) << 3)) << 1);
    const uint32_t bBase = smem_u32(Ws) +
        (((((lane >> 4) << 3) + (lane & 7)) * 40 + (((lane >> 3) & 1) << 3)) << 1);

    float c[NB][4];
#pragma unroll
    for (int nb = 0; nb < NB; nb++)
#pragma unroll
        for (int q = 0; q < 4; q++) c[nb][q] = 0.f;

#pragma unroll
    for (int kc = 0; kc < NKC; kc++)
#pragma unroll
        for (int ks = 0; ks < 2; ks++) {
            uint32_t a0, a1, a2, a3;
            ldsm4(a0, a1, a2, a3, aBase + ((kc * 32 + ks * 16) << 1));
#pragma unroll
            for (int p = 0; p < NB / 2; p++) {
                uint32_t b0, b1, b2, b3;
                ldsm4(b0, b1, b2, b3,
                      bBase + ((((kc * OUTD + p * 16) * 40) + ks * 16) << 1));
                MMA16816(c[2 * p],     a0, a1, a2, a3, b0, b1);
                MMA16816(c[2 * p + 1], a0, a1, a2, a3, b2, b3);
            }
        }

#pragma unroll
    for (int h = 0; h < 2; h++) {
        int pos = pb + wr + gid + 8 * h;
        if (pos < plim) {
            int row = g_perm[pos];
#pragma unroll
            for (int nb = 0; nb < NB; nb++) {
                int col = nb * 8 + 2 * tig;
                float2 b = *(const float2*)(bias + t * OUTD + col);
                float vx = fmaxf(c[nb][2 * h] + b.x, 0.f);
                float vy = fmaxf(c[nb][2 * h + 1] + b.y, 0.f);
                if (HOUT)
                    *(__half2*)(g_Hh + (size_t)row * OUTD + col) = __floats2half2_rn(vx, vy);
                else
                    *(float2*)(out + (size_t)row * OUTD + col) = make_float2(vx, vy);
            }
        }
    }
}

// ===========================================================================
// Edge pass: 4 threads / edge, uint4 fp16 gathers, 2x red.v4.f32 scatter.
// ===========================================================================
template <bool COUNT>
__global__ __launch_bounds__(256) void edge_kernel(const int* __restrict__ ei,
                                                   const int* __restrict__ et, int E) {
    int gid = blockIdx.x * blockDim.x + threadIdx.x;
    int e = gid >> 2;
    if (e >= E) return;
    int l = gid & 3;
    int src = ei[e], dst = ei[E + e], t = et[e];

    uint4 ar = *(const uint4*)(g_ABh + (size_t)src * ABDIM + t * EH + l * 8);
    uint4 br = *(const uint4*)(g_ABh + (size_t)dst * ABDIM + CDIM + t * EH + l * 8);
    float m[8];
#pragma unroll
    for (int q = 0; q < 4; q++) {
        float2 a = __half22float2(*(__half2*)(((uint32_t*)&ar) + q));
        float2 b = __half22float2(*(__half2*)(((uint32_t*)&br) + q));
        m[2 * q]     = fmaxf(a.x + b.x, 0.f);
        m[2 * q + 1] = fmaxf(a.y + b.y, 0.f);
    }

    float* p = g_accum + (size_t)dst * CDIM + t * EH + l * 8;
    asm volatile("red.global.add.v4.f32 [%0], {%1,%2,%3,%4};"
                 :: "l"(p), "f"(m[0]), "f"(m[1]), "f"(m[2]), "f"(m[3]) : "memory");
    asm volatile("red.global.add.v4.f32 [%0], {%1,%2,%3,%4};"
                 :: "l"(p + 4), "f"(m[4]), "f"(m[5]), "f"(m[6]), "f"(m[7]) : "memory");
    if (COUNT && l == 0) atomicAdd(g_cnt + (size_t)dst * NET + t, 1.0f);
}

// ===========================================================================
extern "C" void kernel_launch(void* const* d_in, const int* in_sizes, int n_in,
                              void* d_out, int out_size) {
    const float* nf  = (const float*)d_in[0];
    const int*   ei  = (const int*)  d_in[1];
    const int*   et  = (const int*)  d_in[2];
    const int*   nt  = (const int*)  d_in[3];
    const float* eW0 = (const float*)d_in[4];
    const float* eb0 = (const float*)d_in[5];
    const float* nW0 = (const float*)d_in[6];
    const float* nb0 = (const float*)d_in[7];
    const float* eW1 = (const float*)d_in[8];
    const float* eb1 = (const float*)d_in[9];
    const float* nW1 = (const float*)d_in[10];
    const float* nb1 = (const float*)d_in[11];
    float* out = (float*)d_out;

    const int N = in_sizes[3];
    const int E = in_sizes[2];

    float *pAcc, *pCnt;
    __half *pHh, *pNFh;
    cudaGetSymbolAddress((void**)&pAcc, g_accum);
    cudaGetSymbolAddress((void**)&pCnt, g_cnt);
    cudaGetSymbolAddress((void**)&pHh,  g_Hh);
    cudaGetSymbolAddress((void**)&pNFh, g_NFh);

    const int nb128 = (N + 127) / 128;
    const dim3 g2(nb128, 2);
    const int gNode = nb128 + 1;
    const int gEdge = (E * 4 + 255) / 256;
    const int gN = (N + 255) / 256;

    // dynamic smem: Xs(128*(K+8)*2) + Ws(NKC*CHUNK*40*2)
    constexpr int S_AB0 = 128 * 136 * 2 + 4 * 96 * 40 * 2;   // 65536
    constexpr int S_AB1 = 128 * 72 * 2 + 2 * 96 * 40 * 2;    // 33792
    constexpr int S_N0  = 128 * 104 * 2 + 3 * 64 * 40 * 2;   // 41984
    constexpr int S_N1  = 128 * 104 * 2 + 3 * 128 * 40 * 2;  // 57344
    cudaFuncSetAttribute(ab_gemm<128, 192, 96, OFF_E0, true>,
                         cudaFuncAttributeMaxDynamicSharedMemorySize, S_AB0);
    cudaFuncSetAttribute(ab_gemm<64, 192, 96, OFF_E1, false>,
                         cudaFuncAttributeMaxDynamicSharedMemorySize, S_AB1);
    cudaFuncSetAttribute(node_gemm<128, 64, OFF_N0, true>,
                         cudaFuncAttributeMaxDynamicSharedMemorySize, S_N0);
    cudaFuncSetAttribute(node_gemm<256, 128, OFF_N1, false>,
                         cudaFuncAttributeMaxDynamicSharedMemorySize, S_N1);

    // staging, nf->fp16, node-type partition
    prep_all<<<(73728 + 255) / 256, 256>>>(eW0, nW0, eW1, nW1);
    nf2h<<<(N * 32 + 255) / 256, 256>>>((const float4*)nf, N * 32);
    count_kernel<<<gN, 256>>>(nt, N);
    assign_kernel<<<gN, 256>>>(nt, N);

    // ---------------- layer 0 (128 -> 64) ----------------
    ab_gemm<128, 192, 96, OFF_E0, true><<<g2, 256, S_AB0>>>(pNFh, eb0, N);
    edge_kernel<true><<<gEdge, 256>>>(ei, et, E);
    node_gemm<128, 64, OFF_N0, true><<<gNode, 256, S_N0>>>(pAcc, pCnt, nb0, nullptr, N);

    // ---------------- layer 1 (64 -> 128) ----------------
    ab_gemm<64, 192, 96, OFF_E1, false><<<g2, 256, S_AB1>>>(pHh, eb1, N);
    edge_kernel<false><<<gEdge, 256>>>(ei, et, E);
    node_gemm<256, 128, OFF_N1, false><<<gNode, 256, S_N1>>>(pAcc, pCnt, nb1, out, N);
}